// round 8
// baseline (speedup 1.0000x reference)
#include <cuda_runtime.h>
#include <cuda_bf16.h>
#include <cstdint>
#include <cstddef>

#define H    300
#define B    256
#define NX   128
#define NY   128
#define VY   32000
#define NROWS 32512          /* 127*256 decoder logit rows */
#define KP   312             /* padded K stride in bf16 halves: 624B = 39*16B, conflict-free */
#define HB   76800           /* H*B */

// ------------------------- scratch (device globals) -------------------------
__device__ __align__(16) float          g_hT[2*HB];
__device__ __align__(16) __nv_bfloat16  g_hB[(size_t)NROWS*KP];   // decoder hidden rows (bf16)
__device__ __align__(16) __nv_bfloat16  g_wB[(size_t)VY*KP];      // outW in bf16, padded
__device__ float g_lse[NROWS];
__device__ float g_tl[NROWS];

// ------------------------- PTX helpers -------------------------
__device__ __forceinline__ uint32_t sptr(const void* p) {
    return (uint32_t)__cvta_generic_to_shared(p);
}
__device__ __forceinline__ void mbar_init(uint32_t mbar, uint32_t cnt) {
    asm volatile("mbarrier.init.shared.b64 [%0], %1;" :: "r"(mbar), "r"(cnt) : "memory");
}
__device__ __forceinline__ void mbar_expect_tx(uint32_t mbar, uint32_t bytes) {
    asm volatile("mbarrier.arrive.expect_tx.shared.b64 _, [%0], %1;" :: "r"(mbar), "r"(bytes) : "memory");
}
__device__ __forceinline__ void mbar_wait(uint32_t mbar, uint32_t phase) {
    uint32_t done;
    do {
        asm volatile("{\n\t.reg .pred p;\n\t"
                     "mbarrier.try_wait.parity.shared::cta.b64 p, [%1], %2;\n\t"
                     "selp.b32 %0, 1, 0, p;\n\t}"
                     : "=r"(done) : "r"(mbar), "r"(phase) : "memory");
    } while (!done);
}
__device__ __forceinline__ void bulk_g2s(uint32_t dst, const void* src, uint32_t bytes, uint32_t mbar) {
    asm volatile("cp.async.bulk.shared::cluster.global.mbarrier::complete_tx::bytes [%0], [%1], %2, [%3];"
                 :: "r"(dst), "l"(src), "r"(bytes), "r"(mbar) : "memory");
}
__device__ __forceinline__ void ldmx4(uint32_t* r, uint32_t addr) {
    asm volatile("ldmatrix.sync.aligned.m8n8.x4.shared.b16 {%0,%1,%2,%3}, [%4];"
                 : "=r"(r[0]), "=r"(r[1]), "=r"(r[2]), "=r"(r[3]) : "r"(addr));
}
__device__ __forceinline__ void mma_bf16(float* c, const uint32_t* a, uint32_t b0, uint32_t b1) {
    asm volatile("mma.sync.aligned.m16n8k16.row.col.f32.bf16.bf16.f32 "
                 "{%0,%1,%2,%3},{%4,%5,%6,%7},{%8,%9},{%0,%1,%2,%3};"
                 : "+f"(c[0]), "+f"(c[1]), "+f"(c[2]), "+f"(c[3])
                 : "r"(a[0]), "r"(a[1]), "r"(a[2]), "r"(a[3]), "r"(b0), "r"(b1));
}

// ------------------------- init: zero h0 + zero pad cols of g_hB -------------------------
__global__ void init_kernel() {
    int stride = gridDim.x * blockDim.x;
    int i0 = blockIdx.x * blockDim.x + threadIdx.x;
    for (int i = i0; i < HB; i += stride) g_hT[i] = 0.f;
    // pad halves 300..311 of each g_hB row -> 12 halves = 3 u32 per row
    for (int i = i0; i < NROWS*3; i += stride) {
        int r = i / 3, c = i - r*3;
        *(uint32_t*)((char*)g_hB + (size_t)r*(KP*2) + 600 + c*4) = 0u;
    }
}

// ------------------------- outW fp32 -> bf16 padded -------------------------
__global__ void wconv_kernel(const float* __restrict__ outW) {
    int stride = gridDim.x * blockDim.x;
    for (int i = blockIdx.x * blockDim.x + threadIdx.x; i < VY*KP; i += stride) {
        int v = i / KP, k = i - v*KP;
        g_wB[i] = __float2bfloat16((k < H) ? outW[(size_t)v*H + k] : 0.f);
    }
}

// ------------------------- one recurrence step -------------------------
// out[j][b] = relu(emb[idx[b]][j] + sum_k W[j][k]*hIn[k][b] + bias[j])
// grid (4 b-blocks, 38 j-blocks of 8), block 256 = 64 b x 4 y-groups (2 j each)
__global__ void __launch_bounds__(256) rnn_step(
    const float* __restrict__ emb, const int* __restrict__ idx,
    const float* __restrict__ W,   const float* __restrict__ bias,
    int selIn, int decRow)
{
    __shared__ __align__(16) float sW[8][304];
    __shared__ __align__(16) float sHT[64*32];
    const int tid = threadIdx.x;
    const int bb = blockIdx.x;
    const int j0 = blockIdx.y * 8;
    const float* hIn  = g_hT + selIn * HB;
    float*       hOut = g_hT + (selIn ^ 1) * HB;

    #pragma unroll
    for (int jl = 0; jl < 8; jl++) {
        int j = j0 + jl;
        for (int k = tid; k < 304; k += 256)
            sW[jl][k] = (j < H && k < H) ? W[j*H + k] : 0.f;
    }

    const int bl = tid & 63, y = tid >> 6;
    const int j1 = j0 + 2*y, j2 = j1 + 1;
    float acc1 = 0.f, acc2 = 0.f;

    for (int kt = 0; kt < 10; kt++) {
        const int k0 = kt * 32;
        __syncthreads();
        #pragma unroll
        for (int i = tid; i < 2048; i += 256) {
            int kk = i >> 6, b = i & 63;
            int k = k0 + kk;
            float v = (k < H) ? hIn[k*B + bb*64 + b] : 0.f;
            sHT[b*32 + ((((kk>>2) ^ (b & 7))) << 2) + (kk & 3)] = v;
        }
        __syncthreads();
        const float4* hv4 = (const float4*)(sHT + bl*32);
        const float4* w1  = (const float4*)&sW[2*y][k0];
        const float4* w2  = (const float4*)&sW[2*y+1][k0];
        #pragma unroll
        for (int c = 0; c < 8; c++) {
            float4 h = hv4[c ^ (bl & 7)];
            float4 a = w1[c];
            float4 b4 = w2[c];
            acc1 += h.x*a.x  + h.y*a.y  + h.z*a.z  + h.w*a.w;
            acc2 += h.x*b4.x + h.y*b4.y + h.z*b4.z + h.w*b4.w;
        }
    }

    const int b = bb*64 + bl;
    if (j1 < H) {   // j1 even and < 300 => j2 <= 299
        int ix = idx[b];
        float v1 = fmaxf(acc1 + emb[(size_t)ix*H + j1] + bias[j1], 0.f);
        float v2 = fmaxf(acc2 + emb[(size_t)ix*H + j2] + bias[j2], 0.f);
        hOut[j1*B + b] = v1;
        hOut[j2*B + b] = v2;
        if (decRow >= 0) {
            size_t row = (size_t)(decRow*B + b);
            g_hB[row*KP + j1] = __float2bfloat16(v1);
            g_hB[row*KP + j2] = __float2bfloat16(v2);
        }
    }
}

// ------------------------- target logit gather GEMV -------------------------
__global__ void __launch_bounds__(256) tl_kernel(const int* __restrict__ y,
                                                 const float* __restrict__ outb)
{
    int gw = blockIdx.x * 8 + (threadIdx.x >> 5);
    int lane = threadIdx.x & 31;
    if (gw >= NROWS) return;
    int t = gw >> 8, b = gw & 255;
    int tgt = y[(t+1)*B + b];
    const __nv_bfloat162* hr = (const __nv_bfloat162*)(g_hB + (size_t)gw*KP);
    const __nv_bfloat162* wr = (const __nv_bfloat162*)(g_wB + (size_t)tgt*KP);
    float acc = 0.f;
    for (int k = lane; k < KP/2; k += 32) {
        float2 hv = __bfloat1622float2(hr[k]);
        float2 wv = __bfloat1622float2(wr[k]);
        acc += hv.x*wv.x + hv.y*wv.y;
    }
    #pragma unroll
    for (int s = 16; s; s >>= 1) acc += __shfl_xor_sync(0xffffffffu, acc, s);
    if (lane == 0) g_tl[gw] = acc + __ldg(outb + tgt);
}

// ------------------------- fused GEMM + online log-sum-exp -------------------------
// grid 254 x 128 thr (4 warps as 2x2). CTA: 128 rows, 500 vocab tiles of 64.
#define OFF_A      0
#define OFF_B0     79872
#define OFF_B1     119808
#define OFF_BIAS0  159744
#define OFF_BIAS1  160000
#define OFF_MS     160256
#define OFF_MBAR   162304
#define GSMEM      162368
#define A_BYTES    79872u     /* 128*312*2 */
#define B_BYTES    39936u     /* 64*312*2 */

__global__ void __launch_bounds__(128, 1) gemm_lse_kernel(const float* __restrict__ outb)
{
    extern __shared__ __align__(1024) char sm[];
    __nv_bfloat16* sA = (__nv_bfloat16*)(sm + OFF_A);
    __nv_bfloat16* sB[2] = { (__nv_bfloat16*)(sm + OFF_B0), (__nv_bfloat16*)(sm + OFF_B1) };
    float* sBias[2] = { (float*)(sm + OFF_BIAS0), (float*)(sm + OFF_BIAS1) };
    float* sMS = (float*)(sm + OFF_MS);
    uint64_t* mbar = (uint64_t*)(sm + OFF_MBAR);

    const int tid = threadIdx.x, lane = tid & 31, wid = tid >> 5;
    const int wr = wid >> 1, wc = wid & 1;
    const __nv_bfloat16* gA = g_hB + (size_t)blockIdx.x * 128 * KP;

    if (tid == 0) {
        mbar_init(sptr(&mbar[0]), 1);
        mbar_init(sptr(&mbar[1]), 1);
        mbar_init(sptr(&mbar[2]), 1);
    }
    __syncthreads();
    if (tid == 0) {
        uint32_t mA = sptr(&mbar[0]);
        mbar_expect_tx(mA, A_BYTES);
        bulk_g2s(sptr(sA), gA, A_BYTES, mA);
        uint32_t m0 = sptr(&mbar[1]);
        mbar_expect_tx(m0, B_BYTES + 256);
        bulk_g2s(sptr(sB[0]), g_wB, B_BYTES, m0);
        bulk_g2s(sptr(sBias[0]), outb, 256, m0);
    }

    const uint32_t aBase = sptr(sA) + (uint32_t)(((wr*64 + (lane & 15))*KP + ((lane >> 4) << 3)) * 2);
    const uint32_t bOff  = (uint32_t)(((wc*32 + (lane & 15))*KP + ((lane >> 4) << 3)) * 2);

    float mrow[8], srow[8];
    #pragma unroll
    for (int i = 0; i < 8; i++) { mrow[i] = -1e30f; srow[i] = 0.f; }

    mbar_wait(sptr(&mbar[0]), 0);

    const int colL = wc*32 + ((lane & 3) << 1);
    const int g = lane >> 2;

    for (int t = 0; t < 500; t++) {
        const int buf = t & 1;
        if (tid == 0 && t + 1 < 500) {
            const int nb = buf ^ 1;
            uint32_t mN = sptr(&mbar[1 + nb]);
            mbar_expect_tx(mN, B_BYTES + 256);
            bulk_g2s(sptr(sB[nb]), g_wB + (size_t)(t+1)*64*KP, B_BYTES, mN);
            bulk_g2s(sptr(sBias[nb]), outb + (t+1)*64, 256, mN);
        }
        mbar_wait(sptr(&mbar[1 + buf]), (t >> 1) & 1);

        float c[4][4][4];
        #pragma unroll
        for (int mb = 0; mb < 4; mb++)
            #pragma unroll
            for (int nb = 0; nb < 4; nb++)
                #pragma unroll
                for (int i = 0; i < 4; i++) c[mb][nb][i] = 0.f;

        const uint32_t bB = sptr(sB[buf]) + bOff;
        for (int kc = 0; kc < 19; kc++) {
            uint32_t a[4][4], bfr[2][4];
            #pragma unroll
            for (int mb = 0; mb < 4; mb++)
                ldmx4(a[mb], aBase + (uint32_t)(mb*(16*KP*2) + kc*32));
            #pragma unroll
            for (int p = 0; p < 2; p++)
                ldmx4(bfr[p], bB + (uint32_t)(p*(16*KP*2) + kc*32));
            #pragma unroll
            for (int mb = 0; mb < 4; mb++) {
                #pragma unroll
                for (int nb = 0; nb < 4; nb++) {
                    const int p = nb >> 1, o = nb & 1;
                    mma_bf16(c[mb][nb], a[mb], bfr[p][o], bfr[p][o + 2]);
                }
            }
        }

        // bias + online log-sum-exp update
        float bv[8];
        #pragma unroll
        for (int nb = 0; nb < 4; nb++) {
            bv[nb*2]   = sBias[buf][colL + nb*8];
            bv[nb*2+1] = sBias[buf][colL + nb*8 + 1];
        }
        #pragma unroll
        for (int mb = 0; mb < 4; mb++) {
            #pragma unroll
            for (int h = 0; h < 2; h++) {
                const int s = h << 1;
                float v[8];
                #pragma unroll
                for (int nb = 0; nb < 4; nb++) {
                    v[nb*2]   = c[mb][nb][s]   + bv[nb*2];
                    v[nb*2+1] = c[mb][nb][s+1] + bv[nb*2+1];
                }
                float lm = v[0];
                #pragma unroll
                for (int i = 1; i < 8; i++) lm = fmaxf(lm, v[i]);
                const int r = mb*2 + h;
                float M = fmaxf(mrow[r], lm);
                float acc = srow[r] * __expf(mrow[r] - M);
                #pragma unroll
                for (int i = 0; i < 8; i++) acc += __expf(v[i] - M);
                srow[r] = acc;
                mrow[r] = M;
            }
        }
        __syncthreads();
    }

    // reduce across quad (lane&3) via shuffles, stash per-warp (m,s) in smem
    #pragma unroll
    for (int r = 0; r < 8; r++) {
        float M = mrow[r], S = srow[r];
        #pragma unroll
        for (int d = 1; d <= 2; d <<= 1) {
            float M2 = __shfl_xor_sync(0xffffffffu, M, d);
            float S2 = __shfl_xor_sync(0xffffffffu, S, d);
            float Mn = fmaxf(M, M2);
            S = S * __expf(M - Mn) + S2 * __expf(M2 - Mn);
            M = Mn;
        }
        if ((lane & 3) == 0) {
            int row = wr*64 + (r >> 1)*16 + ((r & 1) << 3) + g;
            sMS[(wc*128 + row)*2]     = M;
            sMS[(wc*128 + row)*2 + 1] = S;
        }
    }
    __syncthreads();
    if (tid < 128) {
        float M0 = sMS[tid*2],         S0 = sMS[tid*2 + 1];
        float M1 = sMS[(128+tid)*2],   S1 = sMS[(128+tid)*2 + 1];
        float M = fmaxf(M0, M1);
        float S = S0 * __expf(M0 - M) + S1 * __expf(M1 - M);
        g_lse[blockIdx.x*128 + tid] = M + __logf(S);
    }
}

// ------------------------- final deterministic reduction -------------------------
__global__ void __launch_bounds__(256) sum_kernel(float* out)
{
    __shared__ float red[256];
    const int tid = threadIdx.x;
    float a = 0.f;
    for (int i = tid; i < NROWS; i += 256) a += g_lse[i] - g_tl[i];
    red[tid] = a;
    __syncthreads();
    for (int s = 128; s; s >>= 1) {
        if (tid < s) red[tid] += red[tid + s];
        __syncthreads();
    }
    if (tid == 0) out[0] = red[0] * (1.f / 256.f);
}

// ------------------------- host launcher -------------------------
extern "C" void kernel_launch(void* const* d_in, const int* in_sizes, int n_in,
                              void* d_out, int out_size)
{
    const int*   x       = (const int*)d_in[0];
    const int*   y       = (const int*)d_in[1];
    const float* enc_emb = (const float*)d_in[2];
    const float* encW    = (const float*)d_in[3];
    const float* encb    = (const float*)d_in[4];
    const float* dec_emb = (const float*)d_in[5];
    const float* decW    = (const float*)d_in[6];
    const float* decb    = (const float*)d_in[7];
    const float* outW    = (const float*)d_in[8];
    const float* outb    = (const float*)d_in[9];

    init_kernel<<<256, 256>>>();
    wconv_kernel<<<1024, 256>>>(outW);

    dim3 gs(4, 38);
    for (int t = 0; t < NX; t++)
        rnn_step<<<gs, 256>>>(enc_emb, x + t*B, encW, encb, t & 1, -1);
    for (int td = 0; td < NY - 1; td++) {
        int s = NX + td;
        rnn_step<<<gs, 256>>>(dec_emb, y + td*B, decW, decb, s & 1, td);
    }

    tl_kernel<<<NROWS/8, 256>>>(y, outb);

    cudaFuncSetAttribute(gemm_lse_kernel, cudaFuncAttributeMaxDynamicSharedMemorySize, GSMEM);
    gemm_lse_kernel<<<254, 128, GSMEM>>>(outb);

    sum_kernel<<<1, 256>>>((float*)d_out);
}

// round 9
// speedup vs baseline: 1.6424x; 1.6424x over previous
#include <cuda_runtime.h>
#include <cuda_bf16.h>
#include <cstdint>
#include <cstddef>

#define H    300
#define B    256
#define NX   128
#define NY   128
#define VY   32000
#define NROWS 32512          /* 127*256 decoder logit rows */
#define KP   312             /* padded K stride in bf16 halves for GEMM */

// ---- persistent recurrence geometry ----
#define GJ   320             /* padded output (j) dimension */
#define GK   304             /* padded input  (k) dimension */
#define BSL  2               /* batch columns per CTA */
#define NCTA 128             /* B / BSL */
#define KCACHE 168           /* Wt k-rows cached in smem */
#define RSMEM ((KCACHE*GJ + 2*GK*BSL + 4*GJ*BSL + GJ)*4)   /* 231424 B */

// ------------------------- scratch (device globals) -------------------------
__device__ __align__(16) __nv_bfloat16  g_hB[(size_t)NROWS*KP];   // decoder hidden rows (bf16)
__device__ __align__(16) __nv_bfloat16  g_wB[(size_t)VY*KP];      // outW in bf16, padded
__device__ __align__(16) float g_WtE[GK*GJ];                      // encW transposed+padded
__device__ __align__(16) float g_WtD[GK*GJ];                      // decW transposed+padded
__device__ float g_lse[NROWS];
__device__ float g_tl[NROWS];

// ------------------------- PTX helpers -------------------------
__device__ __forceinline__ uint32_t sptr(const void* p) {
    return (uint32_t)__cvta_generic_to_shared(p);
}
__device__ __forceinline__ void mbar_init(uint32_t mbar, uint32_t cnt) {
    asm volatile("mbarrier.init.shared.b64 [%0], %1;" :: "r"(mbar), "r"(cnt) : "memory");
}
__device__ __forceinline__ void mbar_expect_tx(uint32_t mbar, uint32_t bytes) {
    asm volatile("mbarrier.arrive.expect_tx.shared.b64 _, [%0], %1;" :: "r"(mbar), "r"(bytes) : "memory");
}
__device__ __forceinline__ void mbar_wait(uint32_t mbar, uint32_t phase) {
    uint32_t done;
    do {
        asm volatile("{\n\t.reg .pred p;\n\t"
                     "mbarrier.try_wait.parity.shared::cta.b64 p, [%1], %2;\n\t"
                     "selp.b32 %0, 1, 0, p;\n\t}"
                     : "=r"(done) : "r"(mbar), "r"(phase) : "memory");
    } while (!done);
}
__device__ __forceinline__ void bulk_g2s(uint32_t dst, const void* src, uint32_t bytes, uint32_t mbar) {
    asm volatile("cp.async.bulk.shared::cluster.global.mbarrier::complete_tx::bytes [%0], [%1], %2, [%3];"
                 :: "r"(dst), "l"(src), "r"(bytes), "r"(mbar) : "memory");
}
__device__ __forceinline__ void ldmx4(uint32_t* r, uint32_t addr) {
    asm volatile("ldmatrix.sync.aligned.m8n8.x4.shared.b16 {%0,%1,%2,%3}, [%4];"
                 : "=r"(r[0]), "=r"(r[1]), "=r"(r[2]), "=r"(r[3]) : "r"(addr));
}
__device__ __forceinline__ void mma_bf16(float* c, const uint32_t* a, uint32_t b0, uint32_t b1) {
    asm volatile("mma.sync.aligned.m16n8k16.row.col.f32.bf16.bf16.f32 "
                 "{%0,%1,%2,%3},{%4,%5,%6,%7},{%8,%9},{%0,%1,%2,%3};"
                 : "+f"(c[0]), "+f"(c[1]), "+f"(c[2]), "+f"(c[3])
                 : "r"(a[0]), "r"(a[1]), "r"(a[2]), "r"(a[3]), "r"(b0), "r"(b1));
}

// ------------------------- init: zero pad cols of g_hB -------------------------
__global__ void init_kernel() {
    int stride = gridDim.x * blockDim.x;
    int i0 = blockIdx.x * blockDim.x + threadIdx.x;
    // pad halves 300..311 of each g_hB row -> 12 halves = 3 u32 per row
    for (int i = i0; i < NROWS*3; i += stride) {
        int r = i / 3, c = i - r*3;
        *(uint32_t*)((char*)g_hB + (size_t)r*(KP*2) + 600 + c*4) = 0u;
    }
}

// ------------------------- outW fp32 -> bf16 padded -------------------------
__global__ void wconv_kernel(const float* __restrict__ outW) {
    int stride = gridDim.x * blockDim.x;
    for (int i = blockIdx.x * blockDim.x + threadIdx.x; i < VY*KP; i += stride) {
        int v = i / KP, k = i - v*KP;
        g_wB[i] = __float2bfloat16((k < H) ? outW[(size_t)v*H + k] : 0.f);
    }
}

// ------------------------- W -> transposed padded Wt[k][j] -------------------------
__global__ void wtrans_kernel(const float* __restrict__ W, float* __restrict__ Wt) {
    int stride = gridDim.x * blockDim.x;
    for (int i = blockIdx.x * blockDim.x + threadIdx.x; i < GK*GJ; i += stride) {
        int k = i / GJ, j = i - k*GJ;
        Wt[i] = (j < H && k < H) ? W[j*H + k] : 0.f;
    }
}

// ------------------------- persistent recurrence -------------------------
// 128 CTAs, each owns batch columns {2c, 2c+1} for all 255 steps. h lives in smem.
// 320 threads: jg = tid%80 (4 j's each), kq = tid/80 (76 k's each).
__global__ void __launch_bounds__(320, 1) rnn_persist(
    const float* __restrict__ enc_emb, const int* __restrict__ x, const float* __restrict__ encb,
    const float* __restrict__ dec_emb, const int* __restrict__ y, const float* __restrict__ decb)
{
    extern __shared__ __align__(16) float sm[];
    float* sWc   = sm;                          // [KCACHE*GJ]
    float* sH    = sm + KCACHE*GJ;              // [2][GK*BSL], layout h[k*BSL + b]
    float* sRed  = sH + 2*GK*BSL;               // [4][GJ/4][4*BSL]
    float* sBias = sRed + 4*GJ*BSL;             // [GJ]

    const int tid = threadIdx.x;
    const int jg = tid % 80, kq = tid / 80;
    const int j4 = jg * 4;
    const int b0 = blockIdx.x * BSL;

    // zero h0
    for (int i = tid; i < GK*BSL; i += 320) sH[i] = 0.f;

    int p = 0;
    for (int t = 0; t < NX + NY - 1; t++) {
        const bool enc = (t < NX);
        const float* Wt  = enc ? g_WtE : g_WtD;
        const float* emb = enc ? enc_emb : dec_emb;
        const int*   idx = enc ? (x + t*B) : (y + (t - NX)*B);

        if (t == 0 || t == NX) {   // (re)load cached W rows + bias
            const float* bsrc = enc ? encb : decb;
            for (int i = tid*4; i < KCACHE*GJ; i += 320*4)
                *(float4*)(sWc + i) = *(const float4*)(Wt + i);
            for (int i = tid; i < GJ; i += 320)
                sBias[i] = (i < H) ? bsrc[i] : 0.f;
            __syncthreads();
        }

        // ---- partial GEMV: acc[jj][bb] over this thread's 76 k's ----
        const int kstart = kq * 76;
        const int c1 = (KCACHE > kstart) ? ((KCACHE - kstart) < 76 ? (KCACHE - kstart) : 76) : 0;
        const float2* hp = (const float2*)(sH + p*(GK*BSL)) + kstart;

        float a00 = 0.f, a01 = 0.f, a10 = 0.f, a11 = 0.f;
        float a20 = 0.f, a21 = 0.f, a30 = 0.f, a31 = 0.f;

        const float* w1 = sWc + kstart*GJ + j4;
        #pragma unroll 4
        for (int kk = 0; kk < c1; kk++) {
            float4 w = *(const float4*)(w1 + kk*GJ);
            float2 h = hp[kk];
            a00 += w.x*h.x; a01 += w.x*h.y;
            a10 += w.y*h.x; a11 += w.y*h.y;
            a20 += w.z*h.x; a21 += w.z*h.y;
            a30 += w.w*h.x; a31 += w.w*h.y;
        }
        const float* w2 = Wt + (kstart + c1)*GJ + j4;
        const float2* hp2 = hp + c1;
        const int c2 = 76 - c1;
        #pragma unroll 8
        for (int kk = 0; kk < c2; kk++) {
            float4 w = *(const float4*)(w2 + kk*GJ);
            float2 h = hp2[kk];
            a00 += w.x*h.x; a01 += w.x*h.y;
            a10 += w.y*h.x; a11 += w.y*h.y;
            a20 += w.z*h.x; a21 += w.z*h.y;
            a30 += w.w*h.x; a31 += w.w*h.y;
        }

        float* r = sRed + kq*(GJ*BSL) + jg*(4*BSL);
        r[0] = a00; r[1] = a01; r[2] = a10; r[3] = a11;
        r[4] = a20; r[5] = a21; r[6] = a30; r[7] = a31;
        __syncthreads();

        // ---- finalize: j = tid (0..303) ----
        if (tid < GK) {
            const int j = tid;
            const int base = (j >> 2)*(4*BSL) + (j & 3)*BSL;
            float* hOut = sH + (p ^ 1)*(GK*BSL);
            #pragma unroll
            for (int b = 0; b < BSL; b++) {
                float s = sRed[base + b] + sRed[GJ*BSL + base + b]
                        + sRed[2*GJ*BSL + base + b] + sRed[3*GJ*BSL + base + b];
                float v = 0.f;
                if (j < H) {
                    int ix = idx[b0 + b];
                    v = fmaxf(s + emb[(size_t)ix*H + j] + sBias[j], 0.f);
                }
                hOut[j*BSL + b] = v;
                if (!enc && j < H) {
                    g_hB[(size_t)((t - NX)*B + b0 + b)*KP + j] = __float2bfloat16(v);
                }
            }
        }
        __syncthreads();
        p ^= 1;
    }
}

// ------------------------- target logit gather GEMV -------------------------
__global__ void __launch_bounds__(256) tl_kernel(const int* __restrict__ y,
                                                 const float* __restrict__ outb)
{
    int gw = blockIdx.x * 8 + (threadIdx.x >> 5);
    int lane = threadIdx.x & 31;
    if (gw >= NROWS) return;
    int t = gw >> 8, b = gw & 255;
    int tgt = y[(t+1)*B + b];
    const __nv_bfloat162* hr = (const __nv_bfloat162*)(g_hB + (size_t)gw*KP);
    const __nv_bfloat162* wr = (const __nv_bfloat162*)(g_wB + (size_t)tgt*KP);
    float acc = 0.f;
    for (int k = lane; k < KP/2; k += 32) {
        float2 hv = __bfloat1622float2(hr[k]);
        float2 wv = __bfloat1622float2(wr[k]);
        acc += hv.x*wv.x + hv.y*wv.y;
    }
    #pragma unroll
    for (int s = 16; s; s >>= 1) acc += __shfl_xor_sync(0xffffffffu, acc, s);
    if (lane == 0) g_tl[gw] = acc + __ldg(outb + tgt);
}

// ------------------------- fused GEMM + online log-sum-exp -------------------------
// grid 254 x 128 thr (4 warps as 2x2). CTA: 128 rows, 500 vocab tiles of 64.
#define OFF_A      0
#define OFF_B0     79872
#define OFF_B1     119808
#define OFF_BIAS0  159744
#define OFF_BIAS1  160000
#define OFF_MS     160256
#define OFF_MBAR   162304
#define GSMEM      162368
#define A_BYTES    79872u     /* 128*312*2 */
#define B_BYTES    39936u     /* 64*312*2 */

__global__ void __launch_bounds__(128, 1) gemm_lse_kernel(const float* __restrict__ outb)
{
    extern __shared__ __align__(1024) char smc[];
    __nv_bfloat16* sA = (__nv_bfloat16*)(smc + OFF_A);
    __nv_bfloat16* sB[2] = { (__nv_bfloat16*)(smc + OFF_B0), (__nv_bfloat16*)(smc + OFF_B1) };
    float* sBias[2] = { (float*)(smc + OFF_BIAS0), (float*)(smc + OFF_BIAS1) };
    float* sMS = (float*)(smc + OFF_MS);
    uint64_t* mbar = (uint64_t*)(smc + OFF_MBAR);

    const int tid = threadIdx.x, lane = tid & 31, wid = tid >> 5;
    const int wr = wid >> 1, wc = wid & 1;
    const __nv_bfloat16* gA = g_hB + (size_t)blockIdx.x * 128 * KP;

    if (tid == 0) {
        mbar_init(sptr(&mbar[0]), 1);
        mbar_init(sptr(&mbar[1]), 1);
        mbar_init(sptr(&mbar[2]), 1);
    }
    __syncthreads();
    if (tid == 0) {
        uint32_t mA = sptr(&mbar[0]);
        mbar_expect_tx(mA, A_BYTES);
        bulk_g2s(sptr(sA), gA, A_BYTES, mA);
        uint32_t m0 = sptr(&mbar[1]);
        mbar_expect_tx(m0, B_BYTES + 256);
        bulk_g2s(sptr(sB[0]), g_wB, B_BYTES, m0);
        bulk_g2s(sptr(sBias[0]), outb, 256, m0);
    }

    const uint32_t aBase = sptr(sA) + (uint32_t)(((wr*64 + (lane & 15))*KP + ((lane >> 4) << 3)) * 2);
    const uint32_t bOff  = (uint32_t)(((wc*32 + (lane & 15))*KP + ((lane >> 4) << 3)) * 2);

    float mrow[8], srow[8];
    #pragma unroll
    for (int i = 0; i < 8; i++) { mrow[i] = -1e30f; srow[i] = 0.f; }

    mbar_wait(sptr(&mbar[0]), 0);

    const int colL = wc*32 + ((lane & 3) << 1);
    const int g = lane >> 2;

    for (int t = 0; t < 500; t++) {
        const int buf = t & 1;
        if (tid == 0 && t + 1 < 500) {
            const int nb = buf ^ 1;
            uint32_t mN = sptr(&mbar[1 + nb]);
            mbar_expect_tx(mN, B_BYTES + 256);
            bulk_g2s(sptr(sB[nb]), g_wB + (size_t)(t+1)*64*KP, B_BYTES, mN);
            bulk_g2s(sptr(sBias[nb]), outb + (t+1)*64, 256, mN);
        }
        mbar_wait(sptr(&mbar[1 + buf]), (t >> 1) & 1);

        float c[4][4][4];
        #pragma unroll
        for (int mb = 0; mb < 4; mb++)
            #pragma unroll
            for (int nb = 0; nb < 4; nb++)
                #pragma unroll
                for (int i = 0; i < 4; i++) c[mb][nb][i] = 0.f;

        const uint32_t bB = sptr(sB[buf]) + bOff;
        for (int kc = 0; kc < 19; kc++) {
            uint32_t a[4][4], bfr[2][4];
            #pragma unroll
            for (int mb = 0; mb < 4; mb++)
                ldmx4(a[mb], aBase + (uint32_t)(mb*(16*KP*2) + kc*32));
            #pragma unroll
            for (int pq = 0; pq < 2; pq++)
                ldmx4(bfr[pq], bB + (uint32_t)(pq*(16*KP*2) + kc*32));
            #pragma unroll
            for (int mb = 0; mb < 4; mb++) {
                #pragma unroll
                for (int nb = 0; nb < 4; nb++) {
                    const int pq = nb >> 1, o = nb & 1;
                    mma_bf16(c[mb][nb], a[mb], bfr[pq][o], bfr[pq][o + 2]);
                }
            }
        }

        // bias + online log-sum-exp update
        float bv[8];
        #pragma unroll
        for (int nb = 0; nb < 4; nb++) {
            bv[nb*2]   = sBias[buf][colL + nb*8];
            bv[nb*2+1] = sBias[buf][colL + nb*8 + 1];
        }
        #pragma unroll
        for (int mb = 0; mb < 4; mb++) {
            #pragma unroll
            for (int hh = 0; hh < 2; hh++) {
                const int s = hh << 1;
                float v[8];
                #pragma unroll
                for (int nb = 0; nb < 4; nb++) {
                    v[nb*2]   = c[mb][nb][s]   + bv[nb*2];
                    v[nb*2+1] = c[mb][nb][s+1] + bv[nb*2+1];
                }
                float lm = v[0];
                #pragma unroll
                for (int i = 1; i < 8; i++) lm = fmaxf(lm, v[i]);
                const int r = mb*2 + hh;
                float M = fmaxf(mrow[r], lm);
                float acc = srow[r] * __expf(mrow[r] - M);
                #pragma unroll
                for (int i = 0; i < 8; i++) acc += __expf(v[i] - M);
                srow[r] = acc;
                mrow[r] = M;
            }
        }
        __syncthreads();
    }

    // reduce across quad (lane&3) via shuffles, stash per-warp (m,s) in smem
    #pragma unroll
    for (int r = 0; r < 8; r++) {
        float M = mrow[r], S = srow[r];
        #pragma unroll
        for (int d = 1; d <= 2; d <<= 1) {
            float M2 = __shfl_xor_sync(0xffffffffu, M, d);
            float S2 = __shfl_xor_sync(0xffffffffu, S, d);
            float Mn = fmaxf(M, M2);
            S = S * __expf(M - Mn) + S2 * __expf(M2 - Mn);
            M = Mn;
        }
        if ((lane & 3) == 0) {
            int row = wr*64 + (r >> 1)*16 + ((r & 1) << 3) + g;
            sMS[(wc*128 + row)*2]     = M;
            sMS[(wc*128 + row)*2 + 1] = S;
        }
    }
    __syncthreads();
    if (tid < 128) {
        float M0 = sMS[tid*2],         S0 = sMS[tid*2 + 1];
        float M1 = sMS[(128+tid)*2],   S1 = sMS[(128+tid)*2 + 1];
        float M = fmaxf(M0, M1);
        float S = S0 * __expf(M0 - M) + S1 * __expf(M1 - M);
        g_lse[blockIdx.x*128 + tid] = M + __logf(S);
    }
}

// ------------------------- final deterministic reduction -------------------------
__global__ void __launch_bounds__(256) sum_kernel(float* out)
{
    __shared__ float red[256];
    const int tid = threadIdx.x;
    float a = 0.f;
    for (int i = tid; i < NROWS; i += 256) a += g_lse[i] - g_tl[i];
    red[tid] = a;
    __syncthreads();
    for (int s = 128; s; s >>= 1) {
        if (tid < s) red[tid] += red[tid + s];
        __syncthreads();
    }
    if (tid == 0) out[0] = red[0] * (1.f / 256.f);
}

// ------------------------- host launcher -------------------------
extern "C" void kernel_launch(void* const* d_in, const int* in_sizes, int n_in,
                              void* d_out, int out_size)
{
    const int*   x       = (const int*)d_in[0];
    const int*   y       = (const int*)d_in[1];
    const float* enc_emb = (const float*)d_in[2];
    const float* encW    = (const float*)d_in[3];
    const float* encb    = (const float*)d_in[4];
    const float* dec_emb = (const float*)d_in[5];
    const float* decW    = (const float*)d_in[6];
    const float* decb    = (const float*)d_in[7];
    const float* outW    = (const float*)d_in[8];
    const float* outb    = (const float*)d_in[9];

    float* wtE; cudaGetSymbolAddress((void**)&wtE, g_WtE);
    float* wtD; cudaGetSymbolAddress((void**)&wtD, g_WtD);

    init_kernel<<<256, 256>>>();
    wconv_kernel<<<1024, 256>>>(outW);
    wtrans_kernel<<<256, 256>>>(encW, wtE);
    wtrans_kernel<<<256, 256>>>(decW, wtD);

    cudaFuncSetAttribute(rnn_persist, cudaFuncAttributeMaxDynamicSharedMemorySize, RSMEM);
    rnn_persist<<<NCTA, 320, RSMEM>>>(enc_emb, x, encb, dec_emb, y, decb);

    tl_kernel<<<NROWS/8, 256>>>(y, outb);

    cudaFuncSetAttribute(gemm_lse_kernel, cudaFuncAttributeMaxDynamicSharedMemorySize, GSMEM);
    gemm_lse_kernel<<<254, 128, GSMEM>>>(outb);

    sum_kernel<<<1, 256>>>((float*)d_out);
}